// round 10
// baseline (speedup 1.0000x reference)
#include <cuda_runtime.h>
#include <cuda_bf16.h>

#define NROWS 131072
#define DIM   256
#define KC    1024
#define BM    128
#define BN    64
#define BD    32

// scratch (static __device__ arrays: allowed; no allocations).
// Referenced from DEVICE code only (host-side &symbol is the shadow — R4 bug).
__device__ __align__(16) float g_cnorm[KC];     // ||codes||^2, XLA-GPU-style reduction
__device__ __align__(16) float g_znorm[NROWS];  // ||z||^2,     XLA-GPU-style reduction
__device__ int g_idx[NROWS];

// packed dual-fp32 FMA (each half is an independent IEEE-754 fp32 FMA chain)
__device__ __forceinline__ unsigned long long fma2(unsigned long long a,
                                                   unsigned long long b,
                                                   unsigned long long c) {
    unsigned long long d;
    asm("fma.rn.f32x2 %0, %1, %2, %3;" : "=l"(d) : "l"(a), "l"(b), "l"(c));
    return d;
}

// ---------------- kernel 0: row squared-norms, XLA:GPU row-reduce emulation ----
// lane t accumulates elements t, t+32, ... ascending. THE R9 CHANGE: the fused
// c*c feeding the reduce-add is CONTRACTED to fma.rn (XLA's LLVM->NVPTX
// pipeline runs with fp-contract on), not round(mul)+round(add).
// Then shfl_down tree 16,8,4,2,1.
__global__ void rownorm_kernel(const float* __restrict__ x, int nrows, int which) {
    float* out = which ? g_znorm : g_cnorm;
    int g = blockIdx.x * blockDim.x + threadIdx.x;
    int row = g >> 5, lane = g & 31;
    if (row >= nrows) return;
    const float* xr = x + (size_t)row * DIM;
    float acc = 0.f;
#pragma unroll
    for (int j = 0; j < DIM / 32; ++j) {
        float v = xr[lane + 32 * j];
        acc = __fmaf_rn(v, v, acc);              // <-- contracted FMA (was mul+add)
    }
#pragma unroll
    for (int off = 16; off; off >>= 1)
        acc = __fadd_rn(acc, __shfl_down_sync(0xffffffffu, acc, off));
    if (lane == 0) out[row] = acc;
}

// ---------------- kernel 1: fused distance GEMM + argmin ------------------------
// G accumulated as an in-order fp32 FMA chain over k (matches cuBLAS SGEMM).
// dist = fadd(fsub(s1, fmul(2, G)), s2)  — the reference's exact rounding chain.
__global__ __launch_bounds__(256, 2)
void vq_argmin_kernel(const float* __restrict__ z, const float* __restrict__ codes) {
    __shared__ float Zs[BD][BM];   // transposed: Zs[d][m], XOR-8 swizzled
    __shared__ float Cs[BD][BM];   // transposed + duplicated: Cs[d][2n..2n+1]

    const int tid = threadIdx.x;
    const int tx = tid & 15;        // code group 0..15  (4 codes each)
    const int ty = tid >> 4;        // row group  0..15  (8 rows each)
    const int r0 = blockIdx.x * BM;

    // loader mapping
    const int f4 = tid & 7;         // which float4 along d
    const int mr = tid >> 3;        // row/code within tile
    const int d0 = f4 << 2;
    const int sw = (f4 & 3) << 3;   // swizzle: 8 * ((d>>2)&3)

    const float* zg = z + (size_t)r0 * DIM;

    float s1v[8];
#pragma unroll
    for (int p = 0; p < 8; ++p) s1v[p] = g_znorm[r0 + ty * 8 + p];

    float bestd[8];
    int   besti[8];
#pragma unroll
    for (int p = 0; p < 8; ++p) { bestd[p] = 3.4e38f; besti[p] = 0; }

    for (int nt = 0; nt < KC / BN; ++nt) {
        const float* cg = codes + (size_t)(nt * BN) * DIM;
        unsigned long long acc[4][4];
#pragma unroll
        for (int p = 0; p < 4; ++p)
#pragma unroll
            for (int j = 0; j < 4; ++j) acc[p][j] = 0ULL;

        for (int dt = 0; dt < DIM / BD; ++dt) {
            __syncthreads();
            // Z tile: 128 rows x 32 d, store transposed+swizzled
#pragma unroll
            for (int k = 0; k < 4; ++k) {
                int m = mr + 32 * k;
                float4 v = *reinterpret_cast<const float4*>(zg + (size_t)m * DIM + dt * BD + d0);
                int col = m ^ sw;
                Zs[d0 + 0][col] = v.x; Zs[d0 + 1][col] = v.y;
                Zs[d0 + 2][col] = v.z; Zs[d0 + 3][col] = v.w;
            }
            // C tile: 64 codes x 32 d, store transposed+duplicated+swizzled
#pragma unroll
            for (int k = 0; k < 2; ++k) {
                int n = mr + 32 * k;
                float4 v = *reinterpret_cast<const float4*>(cg + (size_t)n * DIM + dt * BD + d0);
                int col = (n << 1) ^ sw;
                Cs[d0 + 0][col] = v.x; Cs[d0 + 0][col + 1] = v.x;
                Cs[d0 + 1][col] = v.y; Cs[d0 + 1][col + 1] = v.y;
                Cs[d0 + 2][col] = v.z; Cs[d0 + 2][col + 1] = v.z;
                Cs[d0 + 3][col] = v.w; Cs[d0 + 3][col + 1] = v.w;
            }
            __syncthreads();

#pragma unroll
            for (int d = 0; d < BD; ++d) {     // k ascending: dt*32 + d
                const int sg = ((d >> 2) & 3) << 2;   // swizzle in b64 units
                const unsigned long long* zrow =
                    reinterpret_cast<const unsigned long long*>(&Zs[d][0]);
                const unsigned long long* crow =
                    reinterpret_cast<const unsigned long long*>(&Cs[d][0]);
                const int zb = (ty << 2) ^ sg;
                const int cb = (tx << 2) ^ sg;
                ulonglong2 zA = *reinterpret_cast<const ulonglong2*>(zrow + zb);
                ulonglong2 zB = *reinterpret_cast<const ulonglong2*>(zrow + zb + 2);
                ulonglong2 cA = *reinterpret_cast<const ulonglong2*>(crow + cb);
                ulonglong2 cB = *reinterpret_cast<const ulonglong2*>(crow + cb + 2);
                unsigned long long zp[4] = { zA.x, zA.y, zB.x, zB.y };
                unsigned long long cp[4] = { cA.x, cA.y, cB.x, cB.y };
#pragma unroll
                for (int p = 0; p < 4; ++p)
#pragma unroll
                    for (int j = 0; j < 4; ++j)
                        acc[p][j] = fma2(zp[p], cp[j], acc[p][j]);
            }
        }

        // epilogue: reference rounding chain  (s1 - 2*G) + s2, then running argmin
        float4 cn = *reinterpret_cast<const float4*>(&g_cnorm[nt * BN + (tx << 2)]);
        float cnv[4] = { cn.x, cn.y, cn.z, cn.w };
#pragma unroll
        for (int p = 0; p < 4; ++p)
#pragma unroll
            for (int j = 0; j < 4; ++j) {
                unsigned long long a = acc[p][j];
                float glo = __uint_as_float((unsigned int)(a & 0xffffffffu));
                float ghi = __uint_as_float((unsigned int)(a >> 32));
                int n = nt * BN + (tx << 2) + j;
                int p0 = 2 * p, p1 = 2 * p + 1;
                float dist0 = __fadd_rn(__fsub_rn(s1v[p0], __fmul_rn(2.0f, glo)), cnv[j]);
                float dist1 = __fadd_rn(__fsub_rn(s1v[p1], __fmul_rn(2.0f, ghi)), cnv[j]);
                if (dist0 < bestd[p0]) { bestd[p0] = dist0; besti[p0] = n; }
                if (dist1 < bestd[p1]) { bestd[p1] = dist1; besti[p1] = n; }
            }
    }

    // reduce across the 16 tx-lanes holding the same rows; ties -> lowest index
#pragma unroll
    for (int p = 0; p < 8; ++p) {
        float d = bestd[p]; int i = besti[p];
#pragma unroll
        for (int off = 8; off; off >>= 1) {
            float d2 = __shfl_xor_sync(0xffffffffu, d, off);
            int   i2 = __shfl_xor_sync(0xffffffffu, i, off);
            if (d2 < d || (d2 == d && i2 < i)) { d = d2; i = i2; }
        }
        if (tx == 0) g_idx[r0 + ty * 8 + p] = i;
    }
}

// ---------------- kernel 2: gather + outputs ----------------
__global__ __launch_bounds__(256)
void vq_output_kernel(const float* __restrict__ z, const float* __restrict__ codes,
                      float* __restrict__ out) {
    int g = blockIdx.x * blockDim.x + threadIdx.x;
    int r = g >> 5, lane = g & 31;
    if (r >= NROWS) return;
    int idx = g_idx[r];
    const float4* zr = reinterpret_cast<const float4*>(z + (size_t)r * DIM);
    const float4* cr = reinterpret_cast<const float4*>(codes + (size_t)idx * DIM);
    float4* orow = reinterpret_cast<float4*>(out + (size_t)r * DIM);
    float s = 0.f;
#pragma unroll
    for (int k = 0; k < 2; ++k) {
        float4 zv = zr[lane + 32 * k];
        float4 cv = cr[lane + 32 * k];
        float4 o;
        float dx = __fsub_rn(cv.x, zv.x); o.x = __fadd_rn(zv.x, dx); s = __fmaf_rn(dx, dx, s);
        float dy = __fsub_rn(cv.y, zv.y); o.y = __fadd_rn(zv.y, dy); s = __fmaf_rn(dy, dy, s);
        float dz = __fsub_rn(cv.z, zv.z); o.z = __fadd_rn(zv.z, dz); s = __fmaf_rn(dz, dz, s);
        float dw = __fsub_rn(cv.w, zv.w); o.w = __fadd_rn(zv.w, dw); s = __fmaf_rn(dw, dw, s);
        orow[lane + 32 * k] = o;
    }
#pragma unroll
    for (int off = 16; off; off >>= 1) s += __shfl_xor_sync(0xffffffffu, s, off);
    if (lane == 0) {
        out[(size_t)NROWS * DIM + r] = 1.25f * s * (1.0f / DIM);          // loss
        out[(size_t)NROWS * DIM + NROWS + r] = (float)idx;                // indices
    }
}

extern "C" void kernel_launch(void* const* d_in, const int* in_sizes, int n_in,
                              void* d_out, int out_size) {
    const float* z     = (const float*)d_in[0];
    const float* codes = (const float*)d_in[1];
    // defensive: identify by size (z = 131072*256, codes = 1024*256)
    if (n_in >= 2 && in_sizes[0] == KC * DIM && in_sizes[1] == NROWS * DIM) {
        const float* t = z; z = codes; codes = t;
    }
    float* out = (float*)d_out;
    (void)out_size;

    rownorm_kernel<<<(KC * 32) / 256, 256>>>(codes, KC, 0);
    rownorm_kernel<<<(NROWS * 32) / 256, 256>>>(z, NROWS, 1);
    vq_argmin_kernel<<<NROWS / BM, 256>>>(z, codes);
    vq_output_kernel<<<NROWS * 32 / 256, 256>>>(z, codes, out);
}

// round 13
// speedup vs baseline: 1.7475x; 1.7475x over previous
#include <cuda_runtime.h>
#include <cuda_bf16.h>
#include <cstdint>

#define NROWS 131072
#define DIM   256
#define KC    1024
#define BM    128
#define BN    64
#define NCHUNK (KC / BN)
#define MARGIN 0.0625f

// ---- scratch (device-side references only; host &symbol is the shadow) ----
__device__ __align__(16) float g_cnorm[KC];
__device__ int  g_idx[NROWS];
__device__ int  g_rescue[NROWS];
__device__ int  g_rescue_cnt;
// codes split to bf16 hi/lo, pre-laid as the SMEM B-tile byte image:
// [chunk][kb=k/64][n=0..63][128B row, 16B-unit XOR-swizzled]
__device__ __align__(16) __nv_bfloat16 g_ct_hi[KC * DIM];
__device__ __align__(16) __nv_bfloat16 g_ct_lo[KC * DIM];

// ---- smem byte offsets ----
#define A_HI  0          // 65536: [kb][row 0..127][128B]
#define A_LO  65536      // 65536
#define B_CH  131072     // 32768: [kb][n 0..63][128B]
#define B_CL  163840     // 32768
#define CN    196608     // 4096
#define RED_B 200704     // 2*128 float
#define RED_S 201728     // 2*128 float
#define RED_I 202752     // 2*128 int
#define SMEM_TOTAL 203776

__device__ __forceinline__ uint32_t smem_u32(const void* p) {
    uint32_t a;
    asm("{ .reg .u64 t; cvta.to.shared.u64 t, %1; cvt.u32.u64 %0, t; }" : "=r"(a) : "l"(p));
    return a;
}
__device__ __forceinline__ void ldm4(uint32_t addr, uint32_t& r0, uint32_t& r1,
                                     uint32_t& r2, uint32_t& r3) {
    asm volatile("ldmatrix.sync.aligned.m8n8.x4.shared.b16 {%0,%1,%2,%3}, [%4];"
                 : "=r"(r0), "=r"(r1), "=r"(r2), "=r"(r3) : "r"(addr));
}
__device__ __forceinline__ void mma16816(float* c, uint32_t a0, uint32_t a1, uint32_t a2,
                                         uint32_t a3, uint32_t b0, uint32_t b1) {
    asm volatile("mma.sync.aligned.m16n8k16.row.col.f32.bf16.bf16.f32 "
                 "{%0,%1,%2,%3}, {%4,%5,%6,%7}, {%8,%9}, {%0,%1,%2,%3};"
                 : "+f"(c[0]), "+f"(c[1]), "+f"(c[2]), "+f"(c[3])
                 : "r"(a0), "r"(a1), "r"(a2), "r"(a3), "r"(b0), "r"(b1));
}

// ---------------- kernel 0: ||codes||^2 (validated chain) + counter reset ------
__global__ void cnorm_kernel(const float* __restrict__ codes) {
    int g = blockIdx.x * blockDim.x + threadIdx.x;
    if (g == 0) g_rescue_cnt = 0;
    int row = g >> 5, lane = g & 31;
    if (row >= KC) return;
    const float* xr = codes + (size_t)row * DIM;
    float acc = 0.f;
#pragma unroll
    for (int j = 0; j < DIM / 32; ++j) { float v = xr[lane + 32 * j]; acc = __fmaf_rn(v, v, acc); }
#pragma unroll
    for (int off = 16; off; off >>= 1)
        acc = __fadd_rn(acc, __shfl_down_sync(0xffffffffu, acc, off));
    if (lane == 0) g_cnorm[row] = acc;
}

// ---------------- kernel 0b: split codes bf16 hi/lo into B-tile byte image -----
__global__ void ctile_kernel(const float* __restrict__ codes) {
    for (int idx = blockIdx.x * blockDim.x + threadIdx.x; idx < KC * DIM;
         idx += gridDim.x * blockDim.x) {
        int c = idx >> 8, k = idx & 255;
        float v = codes[idx];
        __nv_bfloat16 h = __float2bfloat16(v);
        __nv_bfloat16 l = __float2bfloat16(__fsub_rn(v, __bfloat162float(h)));
        int chunk = c >> 6, n = c & 63;
        uint32_t kc2 = (uint32_t)(((k & 63) * 2) ^ ((n & 7) << 4));
        size_t e = (size_t)chunk * 16384 + (size_t)(k >> 6) * 4096 + n * 64 + (kc2 >> 1);
        g_ct_hi[e] = h;
        g_ct_lo[e] = l;
    }
}

// ---------------- kernel 1: coarse bf16x3 mma.sync distance + argmin -----------
__global__ __launch_bounds__(256, 1)
void vq_coarse_kernel(const float* __restrict__ z) {
    extern __shared__ char smem[];
    const uint32_t sb = smem_u32(smem);
    const int tid = threadIdx.x, lane = tid & 31, wid = tid >> 5;
    const int wm = wid >> 1, wn = wid & 1;
    const int r0 = blockIdx.x * BM;

    float* cns = (float*)(smem + CN);
    for (int i = tid; i < KC; i += 256) cns[i] = g_cnorm[i];

    // A tiles: split z rows to bf16 hi/lo, store swizzled [kb][row][128B]
    {
        const int row = tid >> 1;
        const int khalf = (tid & 1) * 128;
        const float* zr = z + (size_t)(r0 + row) * DIM;
#pragma unroll
        for (int gq = 0; gq < 16; ++gq) {
            int k0 = khalf + gq * 8;
            float4 v0 = *(const float4*)(zr + k0);
            float4 v1 = *(const float4*)(zr + k0 + 4);
            float vv[8] = { v0.x, v0.y, v0.z, v0.w, v1.x, v1.y, v1.z, v1.w };
            uint32_t hu[4], lu[4];
#pragma unroll
            for (int q = 0; q < 4; ++q) {
                __nv_bfloat16 h0 = __float2bfloat16(vv[2 * q]);
                __nv_bfloat16 h1 = __float2bfloat16(vv[2 * q + 1]);
                __nv_bfloat16 l0 = __float2bfloat16(__fsub_rn(vv[2 * q],     __bfloat162float(h0)));
                __nv_bfloat16 l1 = __float2bfloat16(__fsub_rn(vv[2 * q + 1], __bfloat162float(h1)));
                hu[q] = (uint32_t)__bfloat16_as_ushort(h0) | ((uint32_t)__bfloat16_as_ushort(h1) << 16);
                lu[q] = (uint32_t)__bfloat16_as_ushort(l0) | ((uint32_t)__bfloat16_as_ushort(l1) << 16);
            }
            uint32_t kc2 = (uint32_t)(((k0 & 63) * 2) ^ ((row & 7) << 4));
            uint32_t byte = (uint32_t)((k0 >> 6) * 16384 + row * 128) + kc2;
            *(uint4*)(smem + A_HI + byte) = make_uint4(hu[0], hu[1], hu[2], hu[3]);
            *(uint4*)(smem + A_LO + byte) = make_uint4(lu[0], lu[1], lu[2], lu[3]);
        }
    }

    // per-lane ldmatrix address components
    uint32_t preA[2], xorA[2], preB[2], xorB[2];
#pragma unroll
    for (int mi = 0; mi < 2; ++mi) {
        int rA = wm * 32 + mi * 16 + (lane & 15);
        preA[mi] = (uint32_t)(rA * 128);
        xorA[mi] = (uint32_t)((rA & 7) << 4);
    }
#pragma unroll
    for (int bi = 0; bi < 2; ++bi) {
        int rB = bi * 16 + (lane & 7) + ((lane >> 4) << 3);   // local n within 64-chunk? no: within warp tile below
        // B rows are local code index within the 64-chunk: n_local = wn*32 + bi*16 + (lane&7) + ((lane>>4)<<3)
        rB += wn * 32;
        preB[bi] = (uint32_t)(rB * 128);
        xorB[bi] = (uint32_t)((rB & 7) << 4);
    }
    const uint32_t kA_half = (uint32_t)((lane >> 4) << 4);        // byte offset of k-half for A
    const uint32_t kB_half = (uint32_t)(((lane >> 3) & 1) << 4);  // byte offset of k-half for B

    float best[4], second[4];
    int   bidx[4];
#pragma unroll
    for (int s = 0; s < 4; ++s) { best[s] = 3.4e38f; second[s] = 3.4e38f; bidx[s] = 0; }

    for (int nt = 0; nt < NCHUNK; ++nt) {
        __syncthreads();   // previous chunk's mma reads done before overwriting B
        {
            const uint4* sh = (const uint4*)(g_ct_hi + (size_t)nt * 16384);
            const uint4* sl = (const uint4*)(g_ct_lo + (size_t)nt * 16384);
            uint4* dh = (uint4*)(smem + B_CH);
            uint4* dl = (uint4*)(smem + B_CL);
#pragma unroll
            for (int i = tid; i < 2048; i += 256) { dh[i] = sh[i]; dl[i] = sl[i]; }
        }
        __syncthreads();

        float acc[2][4][4];
#pragma unroll
        for (int mi = 0; mi < 2; ++mi)
#pragma unroll
            for (int ni = 0; ni < 4; ++ni)
#pragma unroll
                for (int q = 0; q < 4; ++q) acc[mi][ni][q] = 0.f;

        // pass 0+1: A=zh vs B=ch and B=cl
#pragma unroll
        for (int ks = 0; ks < 16; ++ks) {
            uint32_t akb = (uint32_t)((ks >> 2) * 16384), bkb = (uint32_t)((ks >> 2) * 8192);
            uint32_t akc = (uint32_t)((ks & 3) * 32) + kA_half;
            uint32_t bkc = (uint32_t)((ks & 3) * 32) + kB_half;
            uint32_t a[2][4], b[2][4];
#pragma unroll
            for (int mi = 0; mi < 2; ++mi)
                ldm4(sb + A_HI + akb + preA[mi] + (akc ^ xorA[mi]),
                     a[mi][0], a[mi][1], a[mi][2], a[mi][3]);
#pragma unroll
            for (int bi = 0; bi < 2; ++bi)
                ldm4(sb + B_CH + bkb + preB[bi] + (bkc ^ xorB[bi]),
                     b[bi][0], b[bi][1], b[bi][2], b[bi][3]);
#pragma unroll
            for (int mi = 0; mi < 2; ++mi)
#pragma unroll
                for (int bi = 0; bi < 2; ++bi) {
                    mma16816(acc[mi][bi * 2 + 0], a[mi][0], a[mi][1], a[mi][2], a[mi][3],
                             b[bi][0], b[bi][1]);
                    mma16816(acc[mi][bi * 2 + 1], a[mi][0], a[mi][1], a[mi][2], a[mi][3],
                             b[bi][2], b[bi][3]);
                }
#pragma unroll
            for (int bi = 0; bi < 2; ++bi)
                ldm4(sb + B_CL + bkb + preB[bi] + (bkc ^ xorB[bi]),
                     b[bi][0], b[bi][1], b[bi][2], b[bi][3]);
#pragma unroll
            for (int mi = 0; mi < 2; ++mi)
#pragma unroll
                for (int bi = 0; bi < 2; ++bi) {
                    mma16816(acc[mi][bi * 2 + 0], a[mi][0], a[mi][1], a[mi][2], a[mi][3],
                             b[bi][0], b[bi][1]);
                    mma16816(acc[mi][bi * 2 + 1], a[mi][0], a[mi][1], a[mi][2], a[mi][3],
                             b[bi][2], b[bi][3]);
                }
        }
        // pass 2: A=zl vs B=ch
#pragma unroll
        for (int ks = 0; ks < 16; ++ks) {
            uint32_t akb = (uint32_t)((ks >> 2) * 16384), bkb = (uint32_t)((ks >> 2) * 8192);
            uint32_t akc = (uint32_t)((ks & 3) * 32) + kA_half;
            uint32_t bkc = (uint32_t)((ks & 3) * 32) + kB_half;
            uint32_t a[2][4], b[2][4];
#pragma unroll
            for (int mi = 0; mi < 2; ++mi)
                ldm4(sb + A_LO + akb + preA[mi] + (akc ^ xorA[mi]),
                     a[mi][0], a[mi][1], a[mi][2], a[mi][3]);
#pragma unroll
            for (int bi = 0; bi < 2; ++bi)
                ldm4(sb + B_CH + bkb + preB[bi] + (bkc ^ xorB[bi]),
                     b[bi][0], b[bi][1], b[bi][2], b[bi][3]);
#pragma unroll
            for (int mi = 0; mi < 2; ++mi)
#pragma unroll
                for (int bi = 0; bi < 2; ++bi) {
                    mma16816(acc[mi][bi * 2 + 0], a[mi][0], a[mi][1], a[mi][2], a[mi][3],
                             b[bi][0], b[bi][1]);
                    mma16816(acc[mi][bi * 2 + 1], a[mi][0], a[mi][1], a[mi][2], a[mi][3],
                             b[bi][2], b[bi][3]);
                }
        }

        // epilogue: dist = cnorm - 2G, running best/second per row-slot
#pragma unroll
        for (int mi = 0; mi < 2; ++mi)
#pragma unroll
            for (int ni = 0; ni < 4; ++ni) {
                int colb = nt * 64 + wn * 32 + ni * 8 + 2 * (lane & 3);
                float cn0 = cns[colb], cn1 = cns[colb + 1];
#pragma unroll
                for (int h = 0; h < 2; ++h) {
                    int s = mi * 2 + h;
                    float d0 = __fmaf_rn(-2.0f, acc[mi][ni][h * 2 + 0], cn0);
                    float d1 = __fmaf_rn(-2.0f, acc[mi][ni][h * 2 + 1], cn1);
                    if (d0 < best[s]) { second[s] = best[s]; best[s] = d0; bidx[s] = colb; }
                    else if (d0 < second[s]) second[s] = d0;
                    if (d1 < best[s]) { second[s] = best[s]; best[s] = d1; bidx[s] = colb + 1; }
                    else if (d1 < second[s]) second[s] = d1;
                }
            }
    }

    // quad reduce (lanes sharing lane>>2 hold the same rows, different cols)
#pragma unroll
    for (int s = 0; s < 4; ++s) {
        float b = best[s], se = second[s]; int i = bidx[s];
#pragma unroll
        for (int off = 1; off <= 2; off <<= 1) {
            float b2 = __shfl_xor_sync(0xffffffffu, b, off);
            float s2 = __shfl_xor_sync(0xffffffffu, se, off);
            int   i2 = __shfl_xor_sync(0xffffffffu, i, off);
            if (b2 < b) { se = fminf(b, s2); b = b2; i = i2; }
            else        { se = fminf(se, b2); }
        }
        best[s] = b; second[s] = se; bidx[s] = i;
    }
    float* rb = (float*)(smem + RED_B);
    float* rs = (float*)(smem + RED_S);
    int*   ri = (int*)(smem + RED_I);
    if ((lane & 3) == 0) {
#pragma unroll
        for (int s = 0; s < 4; ++s) {
            int row = wm * 32 + (lane >> 2) + s * 8;
            rb[wn * 128 + row] = best[s];
            rs[wn * 128 + row] = second[s];
            ri[wn * 128 + row] = bidx[s];
        }
    }
    __syncthreads();
    if (tid < 128) {
        float b0 = rb[tid], s0 = rs[tid]; int i0 = ri[tid];
        float b1 = rb[128 + tid], s1 = rs[128 + tid]; int i1 = ri[128 + tid];
        float b, se; int i;
        if (b1 < b0) { b = b1; i = i1; se = fminf(b0, s1); }
        else         { b = b0; i = i0; se = fminf(b1, s0); }
        int row = r0 + tid;
        g_idx[row] = i;
        if (se - b < MARGIN) {
            int slot = atomicAdd(&g_rescue_cnt, 1);
            if (slot < NROWS) g_rescue[slot] = row;
        }
    }
}

// ---------------- kernel 1b: exact rescue (validated R10 reference chain) ------
__global__ __launch_bounds__(256)
void vq_rescue_kernel(const float* __restrict__ z, const float* __restrict__ codes) {
    __shared__ float zs[DIM];
    __shared__ float s1sh;
    __shared__ float bd[256];
    __shared__ int   bix[256];
    int cnt = g_rescue_cnt;
    if (cnt > NROWS) cnt = NROWS;
    for (int it = blockIdx.x; it < cnt; it += gridDim.x) {
        int r = g_rescue[it];
        if (threadIdx.x < 64)
            ((float4*)zs)[threadIdx.x] = ((const float4*)(z + (size_t)r * DIM))[threadIdx.x];
        __syncthreads();
        if (threadIdx.x < 32) {
            float acc = 0.f;
#pragma unroll
            for (int j = 0; j < DIM / 32; ++j) {
                float v = zs[threadIdx.x + 32 * j];
                acc = __fmaf_rn(v, v, acc);
            }
#pragma unroll
            for (int off = 16; off; off >>= 1)
                acc = __fadd_rn(acc, __shfl_down_sync(0xffffffffu, acc, off));
            if (threadIdx.x == 0) s1sh = acc;
        }
        __syncthreads();
        float s1 = s1sh, best = 3.4e38f;
        int bidx = 0;
        for (int c = threadIdx.x; c < KC; c += 256) {
            const float* cr = codes + (size_t)c * DIM;
            float g = 0.f;
#pragma unroll 8
            for (int k = 0; k < DIM; ++k) g = __fmaf_rn(zs[k], cr[k], g);
            float d = __fadd_rn(__fsub_rn(s1, __fmul_rn(2.0f, g)), g_cnorm[c]);
            if (d < best) { best = d; bidx = c; }
        }
        bd[threadIdx.x] = best; bix[threadIdx.x] = bidx;
        __syncthreads();
        for (int stride = 128; stride; stride >>= 1) {
            if (threadIdx.x < stride) {
                float ob = bd[threadIdx.x + stride]; int oi = bix[threadIdx.x + stride];
                if (ob < bd[threadIdx.x] || (ob == bd[threadIdx.x] && oi < bix[threadIdx.x])) {
                    bd[threadIdx.x] = ob; bix[threadIdx.x] = oi;
                }
            }
            __syncthreads();
        }
        if (threadIdx.x == 0) g_idx[r] = bix[0];
        __syncthreads();
    }
}

// ---------------- kernel 2: gather + outputs (validated) -----------------------
__global__ __launch_bounds__(256)
void vq_output_kernel(const float* __restrict__ z, const float* __restrict__ codes,
                      float* __restrict__ out) {
    int g = blockIdx.x * blockDim.x + threadIdx.x;
    int r = g >> 5, lane = g & 31;
    if (r >= NROWS) return;
    int idx = g_idx[r];
    const float4* zr = reinterpret_cast<const float4*>(z + (size_t)r * DIM);
    const float4* cr = reinterpret_cast<const float4*>(codes + (size_t)idx * DIM);
    float4* orow = reinterpret_cast<float4*>(out + (size_t)r * DIM);
    float s = 0.f;
#pragma unroll
    for (int k = 0; k < 2; ++k) {
        float4 zv = zr[lane + 32 * k];
        float4 cv = cr[lane + 32 * k];
        float4 o;
        float dx = __fsub_rn(cv.x, zv.x); o.x = __fadd_rn(zv.x, dx); s = __fmaf_rn(dx, dx, s);
        float dy = __fsub_rn(cv.y, zv.y); o.y = __fadd_rn(zv.y, dy); s = __fmaf_rn(dy, dy, s);
        float dz = __fsub_rn(cv.z, zv.z); o.z = __fadd_rn(zv.z, dz); s = __fmaf_rn(dz, dz, s);
        float dw = __fsub_rn(cv.w, zv.w); o.w = __fadd_rn(zv.w, dw); s = __fmaf_rn(dw, dw, s);
        orow[lane + 32 * k] = o;
    }
#pragma unroll
    for (int off = 16; off; off >>= 1) s += __shfl_xor_sync(0xffffffffu, s, off);
    if (lane == 0) {
        out[(size_t)NROWS * DIM + r] = 1.25f * s * (1.0f / DIM);
        out[(size_t)NROWS * DIM + NROWS + r] = (float)idx;
    }
}

extern "C" void kernel_launch(void* const* d_in, const int* in_sizes, int n_in,
                              void* d_out, int out_size) {
    const float* z     = (const float*)d_in[0];
    const float* codes = (const float*)d_in[1];
    if (n_in >= 2 && in_sizes[0] == KC * DIM && in_sizes[1] == NROWS * DIM) {
        const float* t = z; z = codes; codes = t;
    }
    float* out = (float*)d_out;
    (void)out_size;

    cudaFuncSetAttribute(vq_coarse_kernel, cudaFuncAttributeMaxDynamicSharedMemorySize,
                         SMEM_TOTAL);

    cnorm_kernel<<<(KC * 32) / 256, 256>>>(codes);
    ctile_kernel<<<256, 256>>>(codes);
    vq_coarse_kernel<<<NROWS / BM, 256, SMEM_TOTAL>>>(z);
    vq_rescue_kernel<<<256, 256>>>(z, codes);
    vq_output_kernel<<<NROWS * 32 / 256, 256>>>(z, codes, out);
}

// round 15
// speedup vs baseline: 1.7882x; 1.0233x over previous
#include <cuda_runtime.h>
#include <cuda_bf16.h>
#include <cstdint>

#define NROWS 131072
#define DIM   256
#define KC    1024
#define BM    128
#define BN    64
#define NCHUNK (KC / BN)
#define MARGIN 0.0625f

// ---- scratch (device-side references only; host &symbol is the shadow) ----
__device__ __align__(16) float g_cnorm[KC];
__device__ int  g_idx[NROWS];
__device__ int  g_rescue[NROWS];
__device__ int  g_rescue_cnt;
// codes split to bf16 hi/lo, pre-laid as the SMEM B-tile byte image:
// [chunk][kb=k/64][n=0..63][128B row, 16B-unit XOR-swizzled]
__device__ __align__(16) __nv_bfloat16 g_ct_hi[KC * DIM];
__device__ __align__(16) __nv_bfloat16 g_ct_lo[KC * DIM];

// ---- smem byte offsets ----
#define A_HI  0          // 65536: [kb][row 0..127][128B]
#define A_LO  65536      // 65536
#define B_CH  131072     // 32768: [kb][n 0..63][128B]
#define B_CL  163840     // 32768
#define DS    196608     // 128 rows x 66 floats (pad) = 33792
#define SMEM_TOTAL 230400

__device__ __forceinline__ uint32_t smem_u32(const void* p) {
    uint32_t a;
    asm("{ .reg .u64 t; cvta.to.shared.u64 t, %1; cvt.u32.u64 %0, t; }" : "=r"(a) : "l"(p));
    return a;
}
__device__ __forceinline__ void ldm4(uint32_t addr, uint32_t& r0, uint32_t& r1,
                                     uint32_t& r2, uint32_t& r3) {
    asm volatile("ldmatrix.sync.aligned.m8n8.x4.shared.b16 {%0,%1,%2,%3}, [%4];"
                 : "=r"(r0), "=r"(r1), "=r"(r2), "=r"(r3) : "r"(addr));
}
__device__ __forceinline__ void mma16816(float* c, uint32_t a0, uint32_t a1, uint32_t a2,
                                         uint32_t a3, uint32_t b0, uint32_t b1) {
    asm volatile("mma.sync.aligned.m16n8k16.row.col.f32.bf16.bf16.f32 "
                 "{%0,%1,%2,%3}, {%4,%5,%6,%7}, {%8,%9}, {%0,%1,%2,%3};"
                 : "+f"(c[0]), "+f"(c[1]), "+f"(c[2]), "+f"(c[3])
                 : "r"(a0), "r"(a1), "r"(a2), "r"(a3), "r"(b0), "r"(b1));
}

// ---------------- kernel 0: ||codes||^2 (validated chain) + counter reset ------
__global__ void cnorm_kernel(const float* __restrict__ codes) {
    int g = blockIdx.x * blockDim.x + threadIdx.x;
    if (g == 0) g_rescue_cnt = 0;
    int row = g >> 5, lane = g & 31;
    if (row >= KC) return;
    const float* xr = codes + (size_t)row * DIM;
    float acc = 0.f;
#pragma unroll
    for (int j = 0; j < DIM / 32; ++j) { float v = xr[lane + 32 * j]; acc = __fmaf_rn(v, v, acc); }
#pragma unroll
    for (int off = 16; off; off >>= 1)
        acc = __fadd_rn(acc, __shfl_down_sync(0xffffffffu, acc, off));
    if (lane == 0) g_cnorm[row] = acc;
}

// ---------------- kernel 0b: split codes bf16 hi/lo into B-tile byte image -----
__global__ void ctile_kernel(const float* __restrict__ codes) {
    for (int idx = blockIdx.x * blockDim.x + threadIdx.x; idx < KC * DIM;
         idx += gridDim.x * blockDim.x) {
        int c = idx >> 8, k = idx & 255;
        float v = codes[idx];
        __nv_bfloat16 h = __float2bfloat16(v);
        __nv_bfloat16 l = __float2bfloat16(__fsub_rn(v, __bfloat162float(h)));
        int chunk = c >> 6, n = c & 63;
        uint32_t kc2 = (uint32_t)(((k & 63) * 2) ^ ((n & 7) << 4));
        size_t e = (size_t)chunk * 16384 + (size_t)(k >> 6) * 4096 + n * 64 + (kc2 >> 1);
        g_ct_hi[e] = h;
        g_ct_lo[e] = l;
    }
}

// ---------------- kernel 1: coarse bf16x3 mma.sync distance + argmin -----------
__global__ __launch_bounds__(256, 1)
void vq_coarse_kernel(const float* __restrict__ z) {
    extern __shared__ char smem[];
    const uint32_t sb = smem_u32(smem);
    const int tid = threadIdx.x, lane = tid & 31, wid = tid >> 5;
    const int wm = wid >> 1, wn = wid & 1;
    const int r0 = blockIdx.x * BM;

    // A tiles: split z rows to bf16 hi/lo, store swizzled [kb][row][128B]
    {
        const int row = tid >> 1;
        const int khalf = (tid & 1) * 128;
        const float* zr = z + (size_t)(r0 + row) * DIM;
#pragma unroll
        for (int gq = 0; gq < 16; ++gq) {
            int k0 = khalf + gq * 8;
            float4 v0 = *(const float4*)(zr + k0);
            float4 v1 = *(const float4*)(zr + k0 + 4);
            float vv[8] = { v0.x, v0.y, v0.z, v0.w, v1.x, v1.y, v1.z, v1.w };
            uint32_t hu[4], lu[4];
#pragma unroll
            for (int q = 0; q < 4; ++q) {
                __nv_bfloat16 h0 = __float2bfloat16(vv[2 * q]);
                __nv_bfloat16 h1 = __float2bfloat16(vv[2 * q + 1]);
                __nv_bfloat16 l0 = __float2bfloat16(__fsub_rn(vv[2 * q],     __bfloat162float(h0)));
                __nv_bfloat16 l1 = __float2bfloat16(__fsub_rn(vv[2 * q + 1], __bfloat162float(h1)));
                hu[q] = (uint32_t)__bfloat16_as_ushort(h0) | ((uint32_t)__bfloat16_as_ushort(h1) << 16);
                lu[q] = (uint32_t)__bfloat16_as_ushort(l0) | ((uint32_t)__bfloat16_as_ushort(l1) << 16);
            }
            uint32_t kc2 = (uint32_t)(((k0 & 63) * 2) ^ ((row & 7) << 4));
            uint32_t byte = (uint32_t)((k0 >> 6) * 16384 + row * 128) + kc2;
            *(uint4*)(smem + A_HI + byte) = make_uint4(hu[0], hu[1], hu[2], hu[3]);
            *(uint4*)(smem + A_LO + byte) = make_uint4(lu[0], lu[1], lu[2], lu[3]);
        }
    }

    // per-lane ldmatrix address components
    uint32_t preA[2], xorA[2], preB[2], xorB[2];
#pragma unroll
    for (int mi = 0; mi < 2; ++mi) {
        int rA = wm * 32 + mi * 16 + (lane & 15);
        preA[mi] = (uint32_t)(rA * 128);
        xorA[mi] = (uint32_t)((rA & 7) << 4);
    }
#pragma unroll
    for (int bi = 0; bi < 2; ++bi) {
        int rB = wn * 32 + bi * 16 + (lane & 7) + ((lane >> 4) << 3);
        preB[bi] = (uint32_t)(rB * 128);
        xorB[bi] = (uint32_t)((rB & 7) << 4);
    }
    const uint32_t kA_half = (uint32_t)((lane >> 4) << 4);
    const uint32_t kB_half = (uint32_t)(((lane >> 3) & 1) << 4);

    // per-row scan state (thread tid<128 owns row r0+tid)
    float bestv = 3.4e38f, secv = 3.4e38f;
    int   besti = 0;

    for (int nt = 0; nt < NCHUNK; ++nt) {
        __syncthreads();   // prior chunk's Ds scan + mma reads done before overwrite
        {
            const uint4* sh = (const uint4*)(g_ct_hi + (size_t)nt * 16384);
            const uint4* sl = (const uint4*)(g_ct_lo + (size_t)nt * 16384);
            uint4* dh = (uint4*)(smem + B_CH);
            uint4* dl = (uint4*)(smem + B_CL);
#pragma unroll
            for (int i = tid; i < 2048; i += 256) { dh[i] = sh[i]; dl[i] = sl[i]; }
        }
        __syncthreads();

        float acc[2][4][4];
#pragma unroll
        for (int mi = 0; mi < 2; ++mi)
#pragma unroll
            for (int ni = 0; ni < 4; ++ni)
#pragma unroll
                for (int q = 0; q < 4; ++q) acc[mi][ni][q] = 0.f;

        // pass 0+1: A=zh vs B=ch and B=cl
#pragma unroll
        for (int ks = 0; ks < 16; ++ks) {
            uint32_t akb = (uint32_t)((ks >> 2) * 16384), bkb = (uint32_t)((ks >> 2) * 8192);
            uint32_t akc = (uint32_t)((ks & 3) * 32) + kA_half;
            uint32_t bkc = (uint32_t)((ks & 3) * 32) + kB_half;
            uint32_t a[2][4], b[2][4];
#pragma unroll
            for (int mi = 0; mi < 2; ++mi)
                ldm4(sb + A_HI + akb + preA[mi] + (akc ^ xorA[mi]),
                     a[mi][0], a[mi][1], a[mi][2], a[mi][3]);
#pragma unroll
            for (int bi = 0; bi < 2; ++bi)
                ldm4(sb + B_CH + bkb + preB[bi] + (bkc ^ xorB[bi]),
                     b[bi][0], b[bi][1], b[bi][2], b[bi][3]);
#pragma unroll
            for (int mi = 0; mi < 2; ++mi)
#pragma unroll
                for (int bi = 0; bi < 2; ++bi) {
                    mma16816(acc[mi][bi * 2 + 0], a[mi][0], a[mi][1], a[mi][2], a[mi][3],
                             b[bi][0], b[bi][1]);
                    mma16816(acc[mi][bi * 2 + 1], a[mi][0], a[mi][1], a[mi][2], a[mi][3],
                             b[bi][2], b[bi][3]);
                }
#pragma unroll
            for (int bi = 0; bi < 2; ++bi)
                ldm4(sb + B_CL + bkb + preB[bi] + (bkc ^ xorB[bi]),
                     b[bi][0], b[bi][1], b[bi][2], b[bi][3]);
#pragma unroll
            for (int mi = 0; mi < 2; ++mi)
#pragma unroll
                for (int bi = 0; bi < 2; ++bi) {
                    mma16816(acc[mi][bi * 2 + 0], a[mi][0], a[mi][1], a[mi][2], a[mi][3],
                             b[bi][0], b[bi][1]);
                    mma16816(acc[mi][bi * 2 + 1], a[mi][0], a[mi][1], a[mi][2], a[mi][3],
                             b[bi][2], b[bi][3]);
                }
        }
        // pass 2: A=zl vs B=ch
#pragma unroll
        for (int ks = 0; ks < 16; ++ks) {
            uint32_t akb = (uint32_t)((ks >> 2) * 16384), bkb = (uint32_t)((ks >> 2) * 8192);
            uint32_t akc = (uint32_t)((ks & 3) * 32) + kA_half;
            uint32_t bkc = (uint32_t)((ks & 3) * 32) + kB_half;
            uint32_t a[2][4], b[2][4];
#pragma unroll
            for (int mi = 0; mi < 2; ++mi)
                ldm4(sb + A_LO + akb + preA[mi] + (akc ^ xorA[mi]),
                     a[mi][0], a[mi][1], a[mi][2], a[mi][3]);
#pragma unroll
            for (int bi = 0; bi < 2; ++bi)
                ldm4(sb + B_CH + bkb + preB[bi] + (bkc ^ xorB[bi]),
                     b[bi][0], b[bi][1], b[bi][2], b[bi][3]);
#pragma unroll
            for (int mi = 0; mi < 2; ++mi)
#pragma unroll
                for (int bi = 0; bi < 2; ++bi) {
                    mma16816(acc[mi][bi * 2 + 0], a[mi][0], a[mi][1], a[mi][2], a[mi][3],
                             b[bi][0], b[bi][1]);
                    mma16816(acc[mi][bi * 2 + 1], a[mi][0], a[mi][1], a[mi][2], a[mi][3],
                             b[bi][2], b[bi][3]);
                }
        }

        // write distances to Ds[row][col] (pad 66 floats/row; STS.64 8B-aligned)
#pragma unroll
        for (int mi = 0; mi < 2; ++mi)
#pragma unroll
            for (int ni = 0; ni < 4; ++ni) {
                int collocal = wn * 32 + ni * 8 + 2 * (lane & 3);
                float2 cn = __ldg((const float2*)(g_cnorm + nt * 64 + collocal));
#pragma unroll
                for (int h = 0; h < 2; ++h) {
                    int row = wm * 32 + mi * 16 + h * 8 + (lane >> 2);
                    float d0 = __fmaf_rn(-2.0f, acc[mi][ni][h * 2 + 0], cn.x);
                    float d1 = __fmaf_rn(-2.0f, acc[mi][ni][h * 2 + 1], cn.y);
                    *(float2*)(smem + DS + (size_t)(row * 66 + collocal) * 4) =
                        make_float2(d0, d1);
                }
            }
        __syncthreads();

        // trivially-correct per-row scan (ascending index; strict < keeps first)
        if (tid < 128) {
            const float2* dr = (const float2*)(smem + DS + (size_t)tid * 264);
            int base = nt * 64;
#pragma unroll
            for (int j = 0; j < 32; ++j) {
                float2 dd = dr[j];
                if (dd.x < bestv) { secv = bestv; bestv = dd.x; besti = base + 2 * j; }
                else if (dd.x < secv) secv = dd.x;
                if (dd.y < bestv) { secv = bestv; bestv = dd.y; besti = base + 2 * j + 1; }
                else if (dd.y < secv) secv = dd.y;
            }
        }
    }

    if (tid < 128) {
        int row = r0 + tid;
        g_idx[row] = besti;
        if (secv - bestv < MARGIN) {
            int slot = atomicAdd(&g_rescue_cnt, 1);
            if (slot < NROWS) g_rescue[slot] = row;
        }
    }
}

// ---------------- kernel 1b: exact rescue (validated R10 reference chain) ------
__global__ __launch_bounds__(256)
void vq_rescue_kernel(const float* __restrict__ z, const float* __restrict__ codes) {
    __shared__ float zs[DIM];
    __shared__ float s1sh;
    __shared__ float bd[256];
    __shared__ int   bix[256];
    int cnt = g_rescue_cnt;
    if (cnt > NROWS) cnt = NROWS;
    for (int it = blockIdx.x; it < cnt; it += gridDim.x) {
        int r = g_rescue[it];
        if (threadIdx.x < 64)
            ((float4*)zs)[threadIdx.x] = ((const float4*)(z + (size_t)r * DIM))[threadIdx.x];
        __syncthreads();
        if (threadIdx.x < 32) {
            float acc = 0.f;
#pragma unroll
            for (int j = 0; j < DIM / 32; ++j) {
                float v = zs[threadIdx.x + 32 * j];
                acc = __fmaf_rn(v, v, acc);
            }
#pragma unroll
            for (int off = 16; off; off >>= 1)
                acc = __fadd_rn(acc, __shfl_down_sync(0xffffffffu, acc, off));
            if (threadIdx.x == 0) s1sh = acc;
        }
        __syncthreads();
        float s1 = s1sh, best = 3.4e38f;
        int bidx = 0;
        for (int c = threadIdx.x; c < KC; c += 256) {
            const float* cr = codes + (size_t)c * DIM;
            float g = 0.f;
#pragma unroll 8
            for (int k = 0; k < DIM; ++k) g = __fmaf_rn(zs[k], cr[k], g);
            float d = __fadd_rn(__fsub_rn(s1, __fmul_rn(2.0f, g)), g_cnorm[c]);
            if (d < best) { best = d; bidx = c; }
        }
        bd[threadIdx.x] = best; bix[threadIdx.x] = bidx;
        __syncthreads();
        for (int stride = 128; stride; stride >>= 1) {
            if (threadIdx.x < stride) {
                float ob = bd[threadIdx.x + stride]; int oi = bix[threadIdx.x + stride];
                if (ob < bd[threadIdx.x] || (ob == bd[threadIdx.x] && oi < bix[threadIdx.x])) {
                    bd[threadIdx.x] = ob; bix[threadIdx.x] = oi;
                }
            }
            __syncthreads();
        }
        if (threadIdx.x == 0) g_idx[r] = bix[0];
        __syncthreads();
    }
}

// ---------------- kernel 2: gather + outputs (validated) -----------------------
__global__ __launch_bounds__(256)
void vq_output_kernel(const float* __restrict__ z, const float* __restrict__ codes,
                      float* __restrict__ out) {
    int g = blockIdx.x * blockDim.x + threadIdx.x;
    int r = g >> 5, lane = g & 31;
    if (r >= NROWS) return;
    int idx = g_idx[r];
    const float4* zr = reinterpret_cast<const float4*>(z + (size_t)r * DIM);
    const float4* cr = reinterpret_cast<const float4*>(codes + (size_t)idx * DIM);
    float4* orow = reinterpret_cast<float4*>(out + (size_t)r * DIM);
    float s = 0.f;
#pragma unroll
    for (int k = 0; k < 2; ++k) {
        float4 zv = zr[lane + 32 * k];
        float4 cv = cr[lane + 32 * k];
        float4 o;
        float dx = __fsub_rn(cv.x, zv.x); o.x = __fadd_rn(zv.x, dx); s = __fmaf_rn(dx, dx, s);
        float dy = __fsub_rn(cv.y, zv.y); o.y = __fadd_rn(zv.y, dy); s = __fmaf_rn(dy, dy, s);
        float dz = __fsub_rn(cv.z, zv.z); o.z = __fadd_rn(zv.z, dz); s = __fmaf_rn(dz, dz, s);
        float dw = __fsub_rn(cv.w, zv.w); o.w = __fadd_rn(zv.w, dw); s = __fmaf_rn(dw, dw, s);
        orow[lane + 32 * k] = o;
    }
#pragma unroll
    for (int off = 16; off; off >>= 1) s += __shfl_xor_sync(0xffffffffu, s, off);
    if (lane == 0) {
        out[(size_t)NROWS * DIM + r] = 1.25f * s * (1.0f / DIM);
        out[(size_t)NROWS * DIM + NROWS + r] = (float)idx;
    }
}

extern "C" void kernel_launch(void* const* d_in, const int* in_sizes, int n_in,
                              void* d_out, int out_size) {
    const float* z     = (const float*)d_in[0];
    const float* codes = (const float*)d_in[1];
    if (n_in >= 2 && in_sizes[0] == KC * DIM && in_sizes[1] == NROWS * DIM) {
        const float* t = z; z = codes; codes = t;
    }
    float* out = (float*)d_out;
    (void)out_size;

    cudaFuncSetAttribute(vq_coarse_kernel, cudaFuncAttributeMaxDynamicSharedMemorySize,
                         SMEM_TOTAL);

    cnorm_kernel<<<(KC * 32) / 256, 256>>>(codes);
    ctile_kernel<<<256, 256>>>(codes);
    vq_coarse_kernel<<<NROWS / BM, 256, SMEM_TOTAL>>>(z);
    vq_rescue_kernel<<<256, 256>>>(z, codes);
    vq_output_kernel<<<NROWS * 32 / 256, 256>>>(z, codes, out);
}

// round 16
// speedup vs baseline: 3.1716x; 1.7736x over previous
#include <cuda_runtime.h>
#include <cuda_bf16.h>
#include <cstdint>

#define NROWS 131072
#define DIM   256
#define KC    1024
#define BM    128
#define BN    64
#define NCHUNK (KC / BN)
#define MARGIN 0.0625f

// ---- scratch (device-side references only; host &symbol is the shadow) ----
__device__ __align__(16) float g_cnorm[KC];
__device__ int  g_idx[NROWS];
__device__ int  g_rescue[NROWS];
__device__ int  g_rescue_cnt;
// codes split to bf16 hi/lo, pre-laid as the SMEM B-tile byte image
__device__ __align__(16) __nv_bfloat16 g_ct_hi[KC * DIM];
__device__ __align__(16) __nv_bfloat16 g_ct_lo[KC * DIM];
// transposed fp32 codebook for the rescue: g_ct_t[k*KC + c]
__device__ __align__(16) float g_ct_t[DIM * KC];

// ---- smem byte offsets ----
#define A_HI  0
#define A_LO  65536
#define B_CH  131072
#define B_CL  163840
#define DS    196608
#define SMEM_TOTAL 230400

__device__ __forceinline__ uint32_t smem_u32(const void* p) {
    uint32_t a;
    asm("{ .reg .u64 t; cvta.to.shared.u64 t, %1; cvt.u32.u64 %0, t; }" : "=r"(a) : "l"(p));
    return a;
}
__device__ __forceinline__ void ldm4(uint32_t addr, uint32_t& r0, uint32_t& r1,
                                     uint32_t& r2, uint32_t& r3) {
    asm volatile("ldmatrix.sync.aligned.m8n8.x4.shared.b16 {%0,%1,%2,%3}, [%4];"
                 : "=r"(r0), "=r"(r1), "=r"(r2), "=r"(r3) : "r"(addr));
}
__device__ __forceinline__ void mma16816(float* c, uint32_t a0, uint32_t a1, uint32_t a2,
                                         uint32_t a3, uint32_t b0, uint32_t b1) {
    asm volatile("mma.sync.aligned.m16n8k16.row.col.f32.bf16.bf16.f32 "
                 "{%0,%1,%2,%3}, {%4,%5,%6,%7}, {%8,%9}, {%0,%1,%2,%3};"
                 : "+f"(c[0]), "+f"(c[1]), "+f"(c[2]), "+f"(c[3])
                 : "r"(a0), "r"(a1), "r"(a2), "r"(a3), "r"(b0), "r"(b1));
}

// ---------------- kernel 0: ||codes||^2 (validated chain) + counter reset ------
__global__ void cnorm_kernel(const float* __restrict__ codes) {
    int g = blockIdx.x * blockDim.x + threadIdx.x;
    if (g == 0) g_rescue_cnt = 0;
    int row = g >> 5, lane = g & 31;
    if (row >= KC) return;
    const float* xr = codes + (size_t)row * DIM;
    float acc = 0.f;
#pragma unroll
    for (int j = 0; j < DIM / 32; ++j) { float v = xr[lane + 32 * j]; acc = __fmaf_rn(v, v, acc); }
#pragma unroll
    for (int off = 16; off; off >>= 1)
        acc = __fadd_rn(acc, __shfl_down_sync(0xffffffffu, acc, off));
    if (lane == 0) g_cnorm[row] = acc;
}

// ---------------- kernel 0b: split codes bf16 hi/lo into B-tile byte image -----
__global__ void ctile_kernel(const float* __restrict__ codes) {
    for (int idx = blockIdx.x * blockDim.x + threadIdx.x; idx < KC * DIM;
         idx += gridDim.x * blockDim.x) {
        int c = idx >> 8, k = idx & 255;
        float v = codes[idx];
        __nv_bfloat16 h = __float2bfloat16(v);
        __nv_bfloat16 l = __float2bfloat16(__fsub_rn(v, __bfloat162float(h)));
        int chunk = c >> 6, n = c & 63;
        uint32_t kc2 = (uint32_t)(((k & 63) * 2) ^ ((n & 7) << 4));
        size_t e = (size_t)chunk * 16384 + (size_t)(k >> 6) * 4096 + n * 64 + (kc2 >> 1);
        g_ct_hi[e] = h;
        g_ct_lo[e] = l;
    }
}

// ---------------- kernel 0c: transposed fp32 codebook (coalesced writes) -------
__global__ void ctrans_kernel(const float* __restrict__ codes) {
    for (int idx = blockIdx.x * blockDim.x + threadIdx.x; idx < KC * DIM;
         idx += gridDim.x * blockDim.x) {
        int k = idx >> 10, c = idx & 1023;
        g_ct_t[idx] = codes[(size_t)c * DIM + k];
    }
}

// ---------------- kernel 1: coarse bf16x3 mma.sync distance + argmin -----------
__global__ __launch_bounds__(256, 1)
void vq_coarse_kernel(const float* __restrict__ z) {
    extern __shared__ char smem[];
    const uint32_t sb = smem_u32(smem);
    const int tid = threadIdx.x, lane = tid & 31, wid = tid >> 5;
    const int wm = wid >> 1, wn = wid & 1;
    const int r0 = blockIdx.x * BM;

    // A tiles: split z rows to bf16 hi/lo, store swizzled [kb][row][128B]
    {
        const int row = tid >> 1;
        const int khalf = (tid & 1) * 128;
        const float* zr = z + (size_t)(r0 + row) * DIM;
#pragma unroll
        for (int gq = 0; gq < 16; ++gq) {
            int k0 = khalf + gq * 8;
            float4 v0 = *(const float4*)(zr + k0);
            float4 v1 = *(const float4*)(zr + k0 + 4);
            float vv[8] = { v0.x, v0.y, v0.z, v0.w, v1.x, v1.y, v1.z, v1.w };
            uint32_t hu[4], lu[4];
#pragma unroll
            for (int q = 0; q < 4; ++q) {
                __nv_bfloat16 h0 = __float2bfloat16(vv[2 * q]);
                __nv_bfloat16 h1 = __float2bfloat16(vv[2 * q + 1]);
                __nv_bfloat16 l0 = __float2bfloat16(__fsub_rn(vv[2 * q],     __bfloat162float(h0)));
                __nv_bfloat16 l1 = __float2bfloat16(__fsub_rn(vv[2 * q + 1], __bfloat162float(h1)));
                hu[q] = (uint32_t)__bfloat16_as_ushort(h0) | ((uint32_t)__bfloat16_as_ushort(h1) << 16);
                lu[q] = (uint32_t)__bfloat16_as_ushort(l0) | ((uint32_t)__bfloat16_as_ushort(l1) << 16);
            }
            uint32_t kc2 = (uint32_t)(((k0 & 63) * 2) ^ ((row & 7) << 4));
            uint32_t byte = (uint32_t)((k0 >> 6) * 16384 + row * 128) + kc2;
            *(uint4*)(smem + A_HI + byte) = make_uint4(hu[0], hu[1], hu[2], hu[3]);
            *(uint4*)(smem + A_LO + byte) = make_uint4(lu[0], lu[1], lu[2], lu[3]);
        }
    }

    // per-lane ldmatrix address components
    uint32_t preA[2], xorA[2], preB[2], xorB[2];
#pragma unroll
    for (int mi = 0; mi < 2; ++mi) {
        int rA = wm * 32 + mi * 16 + (lane & 15);
        preA[mi] = (uint32_t)(rA * 128);
        xorA[mi] = (uint32_t)((rA & 7) << 4);
    }
#pragma unroll
    for (int bi = 0; bi < 2; ++bi) {
        int rB = wn * 32 + bi * 16 + (lane & 7) + ((lane >> 4) << 3);
        preB[bi] = (uint32_t)(rB * 128);
        xorB[bi] = (uint32_t)((rB & 7) << 4);
    }
    const uint32_t kA_half = (uint32_t)((lane >> 4) << 4);
    const uint32_t kB_half = (uint32_t)(((lane >> 3) & 1) << 4);

    float bestv = 3.4e38f, secv = 3.4e38f;
    int   besti = 0;

    for (int nt = 0; nt < NCHUNK; ++nt) {
        __syncthreads();
        {
            const uint4* sh = (const uint4*)(g_ct_hi + (size_t)nt * 16384);
            const uint4* sl = (const uint4*)(g_ct_lo + (size_t)nt * 16384);
            uint4* dh = (uint4*)(smem + B_CH);
            uint4* dl = (uint4*)(smem + B_CL);
#pragma unroll
            for (int i = tid; i < 2048; i += 256) { dh[i] = sh[i]; dl[i] = sl[i]; }
        }
        __syncthreads();

        float acc[2][4][4];
#pragma unroll
        for (int mi = 0; mi < 2; ++mi)
#pragma unroll
            for (int ni = 0; ni < 4; ++ni)
#pragma unroll
                for (int q = 0; q < 4; ++q) acc[mi][ni][q] = 0.f;

        // pass 0+1: A=zh vs B=ch and B=cl
#pragma unroll
        for (int ks = 0; ks < 16; ++ks) {
            uint32_t akb = (uint32_t)((ks >> 2) * 16384), bkb = (uint32_t)((ks >> 2) * 8192);
            uint32_t akc = (uint32_t)((ks & 3) * 32) + kA_half;
            uint32_t bkc = (uint32_t)((ks & 3) * 32) + kB_half;
            uint32_t a[2][4], b[2][4];
#pragma unroll
            for (int mi = 0; mi < 2; ++mi)
                ldm4(sb + A_HI + akb + preA[mi] + (akc ^ xorA[mi]),
                     a[mi][0], a[mi][1], a[mi][2], a[mi][3]);
#pragma unroll
            for (int bi = 0; bi < 2; ++bi)
                ldm4(sb + B_CH + bkb + preB[bi] + (bkc ^ xorB[bi]),
                     b[bi][0], b[bi][1], b[bi][2], b[bi][3]);
#pragma unroll
            for (int mi = 0; mi < 2; ++mi)
#pragma unroll
                for (int bi = 0; bi < 2; ++bi) {
                    mma16816(acc[mi][bi * 2 + 0], a[mi][0], a[mi][1], a[mi][2], a[mi][3],
                             b[bi][0], b[bi][1]);
                    mma16816(acc[mi][bi * 2 + 1], a[mi][0], a[mi][1], a[mi][2], a[mi][3],
                             b[bi][2], b[bi][3]);
                }
#pragma unroll
            for (int bi = 0; bi < 2; ++bi)
                ldm4(sb + B_CL + bkb + preB[bi] + (bkc ^ xorB[bi]),
                     b[bi][0], b[bi][1], b[bi][2], b[bi][3]);
#pragma unroll
            for (int mi = 0; mi < 2; ++mi)
#pragma unroll
                for (int bi = 0; bi < 2; ++bi) {
                    mma16816(acc[mi][bi * 2 + 0], a[mi][0], a[mi][1], a[mi][2], a[mi][3],
                             b[bi][0], b[bi][1]);
                    mma16816(acc[mi][bi * 2 + 1], a[mi][0], a[mi][1], a[mi][2], a[mi][3],
                             b[bi][2], b[bi][3]);
                }
        }
        // pass 2: A=zl vs B=ch
#pragma unroll
        for (int ks = 0; ks < 16; ++ks) {
            uint32_t akb = (uint32_t)((ks >> 2) * 16384), bkb = (uint32_t)((ks >> 2) * 8192);
            uint32_t akc = (uint32_t)((ks & 3) * 32) + kA_half;
            uint32_t bkc = (uint32_t)((ks & 3) * 32) + kB_half;
            uint32_t a[2][4], b[2][4];
#pragma unroll
            for (int mi = 0; mi < 2; ++mi)
                ldm4(sb + A_LO + akb + preA[mi] + (akc ^ xorA[mi]),
                     a[mi][0], a[mi][1], a[mi][2], a[mi][3]);
#pragma unroll
            for (int bi = 0; bi < 2; ++bi)
                ldm4(sb + B_CH + bkb + preB[bi] + (bkc ^ xorB[bi]),
                     b[bi][0], b[bi][1], b[bi][2], b[bi][3]);
#pragma unroll
            for (int mi = 0; mi < 2; ++mi)
#pragma unroll
                for (int bi = 0; bi < 2; ++bi) {
                    mma16816(acc[mi][bi * 2 + 0], a[mi][0], a[mi][1], a[mi][2], a[mi][3],
                             b[bi][0], b[bi][1]);
                    mma16816(acc[mi][bi * 2 + 1], a[mi][0], a[mi][1], a[mi][2], a[mi][3],
                             b[bi][2], b[bi][3]);
                }
        }

        // write distances to Ds[row][col]
#pragma unroll
        for (int mi = 0; mi < 2; ++mi)
#pragma unroll
            for (int ni = 0; ni < 4; ++ni) {
                int collocal = wn * 32 + ni * 8 + 2 * (lane & 3);
                float2 cn = __ldg((const float2*)(g_cnorm + nt * 64 + collocal));
#pragma unroll
                for (int h = 0; h < 2; ++h) {
                    int row = wm * 32 + mi * 16 + h * 8 + (lane >> 2);
                    float d0 = __fmaf_rn(-2.0f, acc[mi][ni][h * 2 + 0], cn.x);
                    float d1 = __fmaf_rn(-2.0f, acc[mi][ni][h * 2 + 1], cn.y);
                    *(float2*)(smem + DS + (size_t)(row * 66 + collocal) * 4) =
                        make_float2(d0, d1);
                }
            }
        __syncthreads();

        if (tid < 128) {
            const float2* dr = (const float2*)(smem + DS + (size_t)tid * 264);
            int base = nt * 64;
#pragma unroll
            for (int j = 0; j < 32; ++j) {
                float2 dd = dr[j];
                if (dd.x < bestv) { secv = bestv; bestv = dd.x; besti = base + 2 * j; }
                else if (dd.x < secv) secv = dd.x;
                if (dd.y < bestv) { secv = bestv; bestv = dd.y; besti = base + 2 * j + 1; }
                else if (dd.y < secv) secv = dd.y;
            }
        }
    }

    if (tid < 128) {
        int row = r0 + tid;
        g_idx[row] = besti;
        if (secv - bestv < MARGIN) {
            int slot = atomicAdd(&g_rescue_cnt, 1);
            if (slot < NROWS) g_rescue[slot] = row;
        }
    }
}

// ---------------- kernel 1b: exact rescue, COALESCED via transposed codebook ---
// Chains are bit-identical to the validated R10 reference arithmetic:
// s1 warp-chain norm; per-code serial k-ascending fmaf; (s1 - 2G) + s2.
__global__ __launch_bounds__(256)
void vq_rescue_kernel(const float* __restrict__ z) {
    __shared__ float zs[DIM];
    __shared__ float s1sh;
    __shared__ float bd[256];
    __shared__ int   bix[256];
    int cnt = g_rescue_cnt;
    if (cnt > NROWS) cnt = NROWS;
    for (int it = blockIdx.x; it < cnt; it += gridDim.x) {
        int r = g_rescue[it];
        if (threadIdx.x < 64)
            ((float4*)zs)[threadIdx.x] = ((const float4*)(z + (size_t)r * DIM))[threadIdx.x];
        __syncthreads();
        if (threadIdx.x < 32) {
            float acc = 0.f;
#pragma unroll
            for (int j = 0; j < DIM / 32; ++j) {
                float v = zs[threadIdx.x + 32 * j];
                acc = __fmaf_rn(v, v, acc);
            }
#pragma unroll
            for (int off = 16; off; off >>= 1)
                acc = __fadd_rn(acc, __shfl_down_sync(0xffffffffu, acc, off));
            if (threadIdx.x == 0) s1sh = acc;
        }
        __syncthreads();
        float s1 = s1sh;
        // 4 interleaved serial chains; lanes read consecutive c -> coalesced
        float g0 = 0.f, g1 = 0.f, g2 = 0.f, g3 = 0.f;
        const float* ct = g_ct_t + threadIdx.x;
#pragma unroll 4
        for (int k = 0; k < DIM; ++k) {
            float zk = zs[k];
            const float* rowp = ct + (size_t)k * KC;
            g0 = __fmaf_rn(zk, rowp[0],   g0);
            g1 = __fmaf_rn(zk, rowp[256], g1);
            g2 = __fmaf_rn(zk, rowp[512], g2);
            g3 = __fmaf_rn(zk, rowp[768], g3);
        }
        float best; int bidx;
        {
            int c = threadIdx.x;
            float d0 = __fadd_rn(__fsub_rn(s1, __fmul_rn(2.0f, g0)), g_cnorm[c]);
            float d1 = __fadd_rn(__fsub_rn(s1, __fmul_rn(2.0f, g1)), g_cnorm[c + 256]);
            float d2 = __fadd_rn(__fsub_rn(s1, __fmul_rn(2.0f, g2)), g_cnorm[c + 512]);
            float d3 = __fadd_rn(__fsub_rn(s1, __fmul_rn(2.0f, g3)), g_cnorm[c + 768]);
            best = d0; bidx = c;                      // ascending c; strict < keeps first
            if (d1 < best) { best = d1; bidx = c + 256; }
            if (d2 < best) { best = d2; bidx = c + 512; }
            if (d3 < best) { best = d3; bidx = c + 768; }
        }
        bd[threadIdx.x] = best; bix[threadIdx.x] = bidx;
        __syncthreads();
        for (int stride = 128; stride; stride >>= 1) {
            if (threadIdx.x < stride) {
                float ob = bd[threadIdx.x + stride]; int oi = bix[threadIdx.x + stride];
                if (ob < bd[threadIdx.x] || (ob == bd[threadIdx.x] && oi < bix[threadIdx.x])) {
                    bd[threadIdx.x] = ob; bix[threadIdx.x] = oi;
                }
            }
            __syncthreads();
        }
        if (threadIdx.x == 0) g_idx[r] = bix[0];
        __syncthreads();
    }
}

// ---------------- kernel 2: gather + outputs (validated) -----------------------
__global__ __launch_bounds__(256)
void vq_output_kernel(const float* __restrict__ z, const float* __restrict__ codes,
                      float* __restrict__ out) {
    int g = blockIdx.x * blockDim.x + threadIdx.x;
    int r = g >> 5, lane = g & 31;
    if (r >= NROWS) return;
    int idx = g_idx[r];
    const float4* zr = reinterpret_cast<const float4*>(z + (size_t)r * DIM);
    const float4* cr = reinterpret_cast<const float4*>(codes + (size_t)idx * DIM);
    float4* orow = reinterpret_cast<float4*>(out + (size_t)r * DIM);
    float s = 0.f;
#pragma unroll
    for (int k = 0; k < 2; ++k) {
        float4 zv = zr[lane + 32 * k];
        float4 cv = cr[lane + 32 * k];
        float4 o;
        float dx = __fsub_rn(cv.x, zv.x); o.x = __fadd_rn(zv.x, dx); s = __fmaf_rn(dx, dx, s);
        float dy = __fsub_rn(cv.y, zv.y); o.y = __fadd_rn(zv.y, dy); s = __fmaf_rn(dy, dy, s);
        float dz = __fsub_rn(cv.z, zv.z); o.z = __fadd_rn(zv.z, dz); s = __fmaf_rn(dz, dz, s);
        float dw = __fsub_rn(cv.w, zv.w); o.w = __fadd_rn(zv.w, dw); s = __fmaf_rn(dw, dw, s);
        orow[lane + 32 * k] = o;
    }
#pragma unroll
    for (int off = 16; off; off >>= 1) s += __shfl_xor_sync(0xffffffffu, s, off);
    if (lane == 0) {
        out[(size_t)NROWS * DIM + r] = 1.25f * s * (1.0f / DIM);
        out[(size_t)NROWS * DIM + NROWS + r] = (float)idx;
    }
}

extern "C" void kernel_launch(void* const* d_in, const int* in_sizes, int n_in,
                              void* d_out, int out_size) {
    const float* z     = (const float*)d_in[0];
    const float* codes = (const float*)d_in[1];
    if (n_in >= 2 && in_sizes[0] == KC * DIM && in_sizes[1] == NROWS * DIM) {
        const float* t = z; z = codes; codes = t;
    }
    float* out = (float*)d_out;
    (void)out_size;

    cudaFuncSetAttribute(vq_coarse_kernel, cudaFuncAttributeMaxDynamicSharedMemorySize,
                         SMEM_TOTAL);

    cnorm_kernel<<<(KC * 32) / 256, 256>>>(codes);
    ctile_kernel<<<256, 256>>>(codes);
    ctrans_kernel<<<256, 256>>>(codes);
    vq_coarse_kernel<<<NROWS / BM, 256, SMEM_TOTAL>>>(z);
    vq_rescue_kernel<<<1024, 256>>>(z);
    vq_output_kernel<<<NROWS * 32 / 256, 256>>>(z, codes, out);
}

// round 17
// speedup vs baseline: 3.6818x; 1.1608x over previous
#include <cuda_runtime.h>
#include <cuda_bf16.h>
#include <cstdint>

#define NROWS 131072
#define DIM   256
#define KC    1024
#define BM    128
#define BN    64
#define NCHUNK (KC / BN)
#define MARGIN 0.03f

// ---- scratch (device-side references only; host &symbol is the shadow) ----
__device__ __align__(16) float g_cnorm[KC];
__device__ int  g_idx[NROWS];
__device__ int  g_rescue[NROWS];
__device__ int  g_rescue_cnt;
// codes split to bf16 hi/lo, pre-laid as the SMEM B-tile byte image
__device__ __align__(16) __nv_bfloat16 g_ct_hi[KC * DIM];
__device__ __align__(16) __nv_bfloat16 g_ct_lo[KC * DIM];
// transposed fp32 codebook for the rescue: g_ct_t[k*KC + c]
__device__ __align__(16) float g_ct_t[DIM * KC];

// ---- smem layout (coarse kernel) ----
// staging: A_HI at 0 (64K), A_LO at 65536 (64K)  — dies after frag preload
// steady : B stage0 at 0 (ch 0..32K, cl 32K..64K), B stage1 at 65536
// DS at 131072 (128 rows x 66 floats)
#define A_HI   0
#define A_LO   65536
#define STAGE(s) ((s) * 65536)
#define DS     131072
#define SMEM_TOTAL 164864

__device__ __forceinline__ uint32_t smem_u32(const void* p) {
    uint32_t a;
    asm("{ .reg .u64 t; cvta.to.shared.u64 t, %1; cvt.u32.u64 %0, t; }" : "=r"(a) : "l"(p));
    return a;
}
__device__ __forceinline__ void ldm4(uint32_t addr, uint32_t& r0, uint32_t& r1,
                                     uint32_t& r2, uint32_t& r3) {
    asm volatile("ldmatrix.sync.aligned.m8n8.x4.shared.b16 {%0,%1,%2,%3}, [%4];"
                 : "=r"(r0), "=r"(r1), "=r"(r2), "=r"(r3) : "r"(addr));
}
__device__ __forceinline__ void mma16816(float* c, uint32_t a0, uint32_t a1, uint32_t a2,
                                         uint32_t a3, uint32_t b0, uint32_t b1) {
    asm volatile("mma.sync.aligned.m16n8k16.row.col.f32.bf16.bf16.f32 "
                 "{%0,%1,%2,%3}, {%4,%5,%6,%7}, {%8,%9}, {%0,%1,%2,%3};"
                 : "+f"(c[0]), "+f"(c[1]), "+f"(c[2]), "+f"(c[3])
                 : "r"(a0), "r"(a1), "r"(a2), "r"(a3), "r"(b0), "r"(b1));
}
__device__ __forceinline__ void cpasync16(uint32_t dst, const void* src) {
    asm volatile("cp.async.cg.shared.global [%0], [%1], 16;" :: "r"(dst), "l"(src));
}

// ---------------- kernel 0: ||codes||^2 (validated chain) + counter reset ------
__global__ void cnorm_kernel(const float* __restrict__ codes) {
    int g = blockIdx.x * blockDim.x + threadIdx.x;
    if (g == 0) g_rescue_cnt = 0;
    int row = g >> 5, lane = g & 31;
    if (row >= KC) return;
    const float* xr = codes + (size_t)row * DIM;
    float acc = 0.f;
#pragma unroll
    for (int j = 0; j < DIM / 32; ++j) { float v = xr[lane + 32 * j]; acc = __fmaf_rn(v, v, acc); }
#pragma unroll
    for (int off = 16; off; off >>= 1)
        acc = __fadd_rn(acc, __shfl_down_sync(0xffffffffu, acc, off));
    if (lane == 0) g_cnorm[row] = acc;
}

// ---------------- kernel 0b: split codes bf16 hi/lo into B-tile byte image -----
__global__ void ctile_kernel(const float* __restrict__ codes) {
    for (int idx = blockIdx.x * blockDim.x + threadIdx.x; idx < KC * DIM;
         idx += gridDim.x * blockDim.x) {
        int c = idx >> 8, k = idx & 255;
        float v = codes[idx];
        __nv_bfloat16 h = __float2bfloat16(v);
        __nv_bfloat16 l = __float2bfloat16(__fsub_rn(v, __bfloat162float(h)));
        int chunk = c >> 6, n = c & 63;
        uint32_t kc2 = (uint32_t)(((k & 63) * 2) ^ ((n & 7) << 4));
        size_t e = (size_t)chunk * 16384 + (size_t)(k >> 6) * 4096 + n * 64 + (kc2 >> 1);
        g_ct_hi[e] = h;
        g_ct_lo[e] = l;
    }
}

// ---------------- kernel 0c: transposed fp32 codebook -------------------------
__global__ void ctrans_kernel(const float* __restrict__ codes) {
    for (int idx = blockIdx.x * blockDim.x + threadIdx.x; idx < KC * DIM;
         idx += gridDim.x * blockDim.x) {
        int k = idx >> 10, c = idx & 1023;
        g_ct_t[idx] = codes[(size_t)c * DIM + k];
    }
}

// ---------------- kernel 1: coarse bf16x3 mma.sync distance + argmin -----------
// Warp w owns rows [16w,16w+16), all 64 cols. A frags (hi+lo, full K) live in
// registers for the whole kernel; B double-buffered via cp.async.
__global__ __launch_bounds__(256, 1)
void vq_coarse_kernel(const float* __restrict__ z) {
    extern __shared__ char smem[];
    const uint32_t sb = smem_u32(smem);
    const int tid = threadIdx.x, lane = tid & 31, wid = tid >> 5;
    const int r0 = blockIdx.x * BM;

    // ---- stage A: split z rows to bf16 hi/lo into staging [kb][row][128B] ----
    {
        const int row = tid >> 1;
        const int khalf = (tid & 1) * 128;
        const float* zr = z + (size_t)(r0 + row) * DIM;
#pragma unroll
        for (int gq = 0; gq < 16; ++gq) {
            int k0 = khalf + gq * 8;
            float4 v0 = *(const float4*)(zr + k0);
            float4 v1 = *(const float4*)(zr + k0 + 4);
            float vv[8] = { v0.x, v0.y, v0.z, v0.w, v1.x, v1.y, v1.z, v1.w };
            uint32_t hu[4], lu[4];
#pragma unroll
            for (int q = 0; q < 4; ++q) {
                __nv_bfloat16 h0 = __float2bfloat16(vv[2 * q]);
                __nv_bfloat16 h1 = __float2bfloat16(vv[2 * q + 1]);
                __nv_bfloat16 l0 = __float2bfloat16(__fsub_rn(vv[2 * q],     __bfloat162float(h0)));
                __nv_bfloat16 l1 = __float2bfloat16(__fsub_rn(vv[2 * q + 1], __bfloat162float(h1)));
                hu[q] = (uint32_t)__bfloat16_as_ushort(h0) | ((uint32_t)__bfloat16_as_ushort(h1) << 16);
                lu[q] = (uint32_t)__bfloat16_as_ushort(l0) | ((uint32_t)__bfloat16_as_ushort(l1) << 16);
            }
            uint32_t kc2 = (uint32_t)(((k0 & 63) * 2) ^ ((row & 7) << 4));
            uint32_t byte = (uint32_t)((k0 >> 6) * 16384 + row * 128) + kc2;
            *(uint4*)(smem + A_HI + byte) = make_uint4(hu[0], hu[1], hu[2], hu[3]);
            *(uint4*)(smem + A_LO + byte) = make_uint4(lu[0], lu[1], lu[2], lu[3]);
        }
    }
    __syncthreads();

    // ---- preload ALL A fragments to registers (once) ----
    uint32_t Ahi[16][4], Alo[16][4];
    {
        int rA = wid * 16 + (lane & 15);
        uint32_t preA = (uint32_t)(rA * 128);
        uint32_t xorA = (uint32_t)((rA & 7) << 4);
        uint32_t kAh  = (uint32_t)((lane >> 4) << 4);
#pragma unroll
        for (int ks = 0; ks < 16; ++ks) {
            uint32_t off = (uint32_t)((ks >> 2) * 16384) + preA +
                           ((((uint32_t)(ks & 3) * 32) + kAh) ^ xorA);
            ldm4(sb + A_HI + off, Ahi[ks][0], Ahi[ks][1], Ahi[ks][2], Ahi[ks][3]);
            ldm4(sb + A_LO + off, Alo[ks][0], Alo[ks][1], Alo[ks][2], Alo[ks][3]);
        }
    }
    __syncthreads();   // all preloads done before B copies overwrite staging

    // ---- B fragment addressing ----
    uint32_t preB[4], xorB[4];
#pragma unroll
    for (int bi = 0; bi < 4; ++bi) {
        int rB = bi * 16 + (lane & 7) + ((lane >> 4) << 3);
        preB[bi] = (uint32_t)(rB * 128);
        xorB[bi] = (uint32_t)((rB & 7) << 4);
    }
    const uint32_t kBh = (uint32_t)(((lane >> 3) & 1) << 4);

    // ---- prologue: async-copy chunk 0 into stage 0 ----
    {
        const char* sh = (const char*)g_ct_hi;
        const char* sl = (const char*)g_ct_lo;
#pragma unroll
        for (int i = tid; i < 2048; i += 256) {
            cpasync16(sb + STAGE(0) + i * 16,         sh + i * 16);
            cpasync16(sb + STAGE(0) + 32768 + i * 16, sl + i * 16);
        }
        asm volatile("cp.async.commit_group;");
    }

    float bestv = 3.4e38f, secv = 3.4e38f;
    int   besti = 0;

    for (int nt = 0; nt < NCHUNK; ++nt) {
        if (nt + 1 < NCHUNK) {
            const char* sh = (const char*)g_ct_hi + (size_t)(nt + 1) * 32768;
            const char* sl = (const char*)g_ct_lo + (size_t)(nt + 1) * 32768;
            uint32_t dstb = sb + STAGE((nt + 1) & 1);
#pragma unroll
            for (int i = tid; i < 2048; i += 256) {
                cpasync16(dstb + i * 16,         sh + i * 16);
                cpasync16(dstb + 32768 + i * 16, sl + i * 16);
            }
            asm volatile("cp.async.commit_group;");
            asm volatile("cp.async.wait_group 1;");
        } else {
            asm volatile("cp.async.wait_group 0;");
        }
        __syncthreads();

        const uint32_t bch = sb + STAGE(nt & 1);
        const uint32_t bcl = bch + 32768;

        float acc[8][4];
#pragma unroll
        for (int ni = 0; ni < 8; ++ni)
#pragma unroll
            for (int q = 0; q < 4; ++q) acc[ni][q] = 0.f;

#pragma unroll
        for (int ks = 0; ks < 16; ++ks) {
            uint32_t kb = (uint32_t)((ks >> 2) * 8192);
            uint32_t kc = (uint32_t)((ks & 3) * 32) + kBh;
            uint32_t b[4][4];
            // B_ch fragments (all 64 cols)
#pragma unroll
            for (int bi = 0; bi < 4; ++bi)
                ldm4(bch + kb + preB[bi] + (kc ^ xorB[bi]),
                     b[bi][0], b[bi][1], b[bi][2], b[bi][3]);
            // zh·ch and zl·ch (reuse ch frags)
#pragma unroll
            for (int bi = 0; bi < 4; ++bi) {
                mma16816(acc[2 * bi + 0], Ahi[ks][0], Ahi[ks][1], Ahi[ks][2], Ahi[ks][3],
                         b[bi][0], b[bi][1]);
                mma16816(acc[2 * bi + 1], Ahi[ks][0], Ahi[ks][1], Ahi[ks][2], Ahi[ks][3],
                         b[bi][2], b[bi][3]);
            }
#pragma unroll
            for (int bi = 0; bi < 4; ++bi) {
                mma16816(acc[2 * bi + 0], Alo[ks][0], Alo[ks][1], Alo[ks][2], Alo[ks][3],
                         b[bi][0], b[bi][1]);
                mma16816(acc[2 * bi + 1], Alo[ks][0], Alo[ks][1], Alo[ks][2], Alo[ks][3],
                         b[bi][2], b[bi][3]);
            }
            // B_cl fragments, zh·cl
#pragma unroll
            for (int bi = 0; bi < 4; ++bi)
                ldm4(bcl + kb + preB[bi] + (kc ^ xorB[bi]),
                     b[bi][0], b[bi][1], b[bi][2], b[bi][3]);
#pragma unroll
            for (int bi = 0; bi < 4; ++bi) {
                mma16816(acc[2 * bi + 0], Ahi[ks][0], Ahi[ks][1], Ahi[ks][2], Ahi[ks][3],
                         b[bi][0], b[bi][1]);
                mma16816(acc[2 * bi + 1], Ahi[ks][0], Ahi[ks][1], Ahi[ks][2], Ahi[ks][3],
                         b[bi][2], b[bi][3]);
            }
        }

        // write distances to Ds[row][col]
#pragma unroll
        for (int ni = 0; ni < 8; ++ni) {
            int col = ni * 8 + 2 * (lane & 3);
            float2 cn = __ldg((const float2*)(g_cnorm + nt * 64 + col));
            int row0 = wid * 16 + (lane >> 2);
            int row1 = row0 + 8;
            *(float2*)(smem + DS + (size_t)(row0 * 66 + col) * 4) =
                make_float2(__fmaf_rn(-2.0f, acc[ni][0], cn.x),
                            __fmaf_rn(-2.0f, acc[ni][1], cn.y));
            *(float2*)(smem + DS + (size_t)(row1 * 66 + col) * 4) =
                make_float2(__fmaf_rn(-2.0f, acc[ni][2], cn.x),
                            __fmaf_rn(-2.0f, acc[ni][3], cn.y));
        }
        __syncthreads();

        // trivially-correct per-row scan (ascending index; strict < keeps first)
        if (tid < 128) {
            const float2* dr = (const float2*)(smem + DS + (size_t)tid * 264);
            int base = nt * 64;
#pragma unroll
            for (int j = 0; j < 32; ++j) {
                float2 dd = dr[j];
                if (dd.x < bestv) { secv = bestv; bestv = dd.x; besti = base + 2 * j; }
                else if (dd.x < secv) secv = dd.x;
                if (dd.y < bestv) { secv = bestv; bestv = dd.y; besti = base + 2 * j + 1; }
                else if (dd.y < secv) secv = dd.y;
            }
        }
    }

    if (tid < 128) {
        int row = r0 + tid;
        g_idx[row] = besti;
        if (secv - bestv < MARGIN) {
            int slot = atomicAdd(&g_rescue_cnt, 1);
            if (slot < NROWS) g_rescue[slot] = row;
        }
    }
}

// ---------------- kernel 1b: exact rescue, coalesced (validated) ---------------
__global__ __launch_bounds__(256)
void vq_rescue_kernel(const float* __restrict__ z) {
    __shared__ float zs[DIM];
    __shared__ float s1sh;
    __shared__ float bd[256];
    __shared__ int   bix[256];
    int cnt = g_rescue_cnt;
    if (cnt > NROWS) cnt = NROWS;
    for (int it = blockIdx.x; it < cnt; it += gridDim.x) {
        int r = g_rescue[it];
        if (threadIdx.x < 64)
            ((float4*)zs)[threadIdx.x] = ((const float4*)(z + (size_t)r * DIM))[threadIdx.x];
        __syncthreads();
        if (threadIdx.x < 32) {
            float acc = 0.f;
#pragma unroll
            for (int j = 0; j < DIM / 32; ++j) {
                float v = zs[threadIdx.x + 32 * j];
                acc = __fmaf_rn(v, v, acc);
            }
#pragma unroll
            for (int off = 16; off; off >>= 1)
                acc = __fadd_rn(acc, __shfl_down_sync(0xffffffffu, acc, off));
            if (threadIdx.x == 0) s1sh = acc;
        }
        __syncthreads();
        float s1 = s1sh;
        float g0 = 0.f, g1 = 0.f, g2 = 0.f, g3 = 0.f;
        const float* ct = g_ct_t + threadIdx.x;
#pragma unroll 4
        for (int k = 0; k < DIM; ++k) {
            float zk = zs[k];
            const float* rowp = ct + (size_t)k * KC;
            g0 = __fmaf_rn(zk, rowp[0],   g0);
            g1 = __fmaf_rn(zk, rowp[256], g1);
            g2 = __fmaf_rn(zk, rowp[512], g2);
            g3 = __fmaf_rn(zk, rowp[768], g3);
        }
        float best; int bidx;
        {
            int c = threadIdx.x;
            float d0 = __fadd_rn(__fsub_rn(s1, __fmul_rn(2.0f, g0)), g_cnorm[c]);
            float d1 = __fadd_rn(__fsub_rn(s1, __fmul_rn(2.0f, g1)), g_cnorm[c + 256]);
            float d2 = __fadd_rn(__fsub_rn(s1, __fmul_rn(2.0f, g2)), g_cnorm[c + 512]);
            float d3 = __fadd_rn(__fsub_rn(s1, __fmul_rn(2.0f, g3)), g_cnorm[c + 768]);
            best = d0; bidx = c;
            if (d1 < best) { best = d1; bidx = c + 256; }
            if (d2 < best) { best = d2; bidx = c + 512; }
            if (d3 < best) { best = d3; bidx = c + 768; }
        }
        bd[threadIdx.x] = best; bix[threadIdx.x] = bidx;
        __syncthreads();
        for (int stride = 128; stride; stride >>= 1) {
            if (threadIdx.x < stride) {
                float ob = bd[threadIdx.x + stride]; int oi = bix[threadIdx.x + stride];
                if (ob < bd[threadIdx.x] || (ob == bd[threadIdx.x] && oi < bix[threadIdx.x])) {
                    bd[threadIdx.x] = ob; bix[threadIdx.x] = oi;
                }
            }
            __syncthreads();
        }
        if (threadIdx.x == 0) g_idx[r] = bix[0];
        __syncthreads();
    }
}

// ---------------- kernel 2: gather + outputs (validated) -----------------------
__global__ __launch_bounds__(256)
void vq_output_kernel(const float* __restrict__ z, const float* __restrict__ codes,
                      float* __restrict__ out) {
    int g = blockIdx.x * blockDim.x + threadIdx.x;
    int r = g >> 5, lane = g & 31;
    if (r >= NROWS) return;
    int idx = g_idx[r];
    const float4* zr = reinterpret_cast<const float4*>(z + (size_t)r * DIM);
    const float4* cr = reinterpret_cast<const float4*>(codes + (size_t)idx * DIM);
    float4* orow = reinterpret_cast<float4*>(out + (size_t)r * DIM);
    float s = 0.f;
#pragma unroll
    for (int k = 0; k < 2; ++k) {
        float4 zv = zr[lane + 32 * k];
        float4 cv = cr[lane + 32 * k];
        float4 o;
        float dx = __fsub_rn(cv.x, zv.x); o.x = __fadd_rn(zv.x, dx); s = __fmaf_rn(dx, dx, s);
        float dy = __fsub_rn(cv.y, zv.y); o.y = __fadd_rn(zv.y, dy); s = __fmaf_rn(dy, dy, s);
        float dz = __fsub_rn(cv.z, zv.z); o.z = __fadd_rn(zv.z, dz); s = __fmaf_rn(dz, dz, s);
        float dw = __fsub_rn(cv.w, zv.w); o.w = __fadd_rn(zv.w, dw); s = __fmaf_rn(dw, dw, s);
        orow[lane + 32 * k] = o;
    }
#pragma unroll
    for (int off = 16; off; off >>= 1) s += __shfl_xor_sync(0xffffffffu, s, off);
    if (lane == 0) {
        out[(size_t)NROWS * DIM + r] = 1.25f * s * (1.0f / DIM);
        out[(size_t)NROWS * DIM + NROWS + r] = (float)idx;
    }
}

extern "C" void kernel_launch(void* const* d_in, const int* in_sizes, int n_in,
                              void* d_out, int out_size) {
    const float* z     = (const float*)d_in[0];
    const float* codes = (const float*)d_in[1];
    if (n_in >= 2 && in_sizes[0] == KC * DIM && in_sizes[1] == NROWS * DIM) {
        const float* t = z; z = codes; codes = t;
    }
    float* out = (float*)d_out;
    (void)out_size;

    cudaFuncSetAttribute(vq_coarse_kernel, cudaFuncAttributeMaxDynamicSharedMemorySize,
                         SMEM_TOTAL);

    cnorm_kernel<<<(KC * 32) / 256, 256>>>(codes);
    ctile_kernel<<<512, 256>>>(codes);
    ctrans_kernel<<<512, 256>>>(codes);
    vq_coarse_kernel<<<NROWS / BM, 256, SMEM_TOTAL>>>(z);
    vq_rescue_kernel<<<1024, 256>>>(z);
    vq_output_kernel<<<NROWS * 32 / 256, 256>>>(z, codes, out);
}